// round 10
// baseline (speedup 1.0000x reference)
#include <cuda_runtime.h>
#include <cuda_fp16.h>
#include <cstdint>

// ---------------- problem constants ----------------
#define NROWS 65536          // B*H*W
#define DDIM  128
#define KCODE 4096
#define TM    128            // rows per CTA
#define TN    128            // codes per tile
#define NT    (KCODE / TN)   // 32 tiles
#define HW    4096
#define BATCH 16
#define NELEM (BATCH * DDIM * HW)   // 8388608
#define NCAND 96             // 32 streams x top-3
#define EPSF  1.0f

// ---------------- device scratch (no allocs allowed) ----------------
__device__ uint4  g_zh4[NROWS * 16];      // fp16(-2z), 256B/row
__device__ uint4  g_eh4[KCODE * 16];      // fp16(e),   256B/row
__device__ float  g_enorm[KCODE];
__device__ int    g_cand[NROWS * NCAND];
__device__ float  g_candv[NROWS * NCAND];
__device__ int    g_idx[NROWS];
__device__ double g_loss;

// ---------------- smem layout ----------------
#define SA    0                 // A tile 128x128 fp16  (32768)
#define SB    32768             // B tiles x2           (65536)
#define SMEM_TOT (32768 + 65536 + 1024)

static __device__ __forceinline__ uint32_t smem_u32(const void* p) {
    uint32_t a;
    asm("{ .reg .u64 t; cvta.to.shared.u64 t, %1; cvt.u32.u64 %0, t; }" : "=r"(a) : "l"(p));
    return a;
}
static __device__ __forceinline__ void ldsm4(uint32_t a[4], uint32_t addr) {
    asm volatile("ldmatrix.sync.aligned.m8n8.x4.shared.b16 {%0,%1,%2,%3}, [%4];"
                 : "=r"(a[0]), "=r"(a[1]), "=r"(a[2]), "=r"(a[3]) : "r"(addr));
}
// fp16 x fp16 -> fp16 accumulator (half-rate-class legacy HMMA)
static __device__ __forceinline__ void mma16816h(uint32_t c[2], const uint32_t a[4],
                                                 uint32_t b0, uint32_t b1) {
    asm volatile("mma.sync.aligned.m16n8k16.row.col.f16.f16.f16.f16 "
                 "{%0,%1}, {%2,%3,%4,%5}, {%6,%7}, {%0,%1};"
                 : "+r"(c[0]), "+r"(c[1])
                 : "r"(a[0]), "r"(a[1]), "r"(a[2]), "r"(a[3]), "r"(b0), "r"(b1));
}
#define CP_ASYNC16(dst, src) \
    asm volatile("cp.async.cg.shared.global [%0], [%1], 16;" :: "r"(dst), "l"(src) : "memory")
#define CP_COMMIT() asm volatile("cp.async.commit_group;" ::: "memory")
#define CP_WAIT(N)  asm volatile("cp.async.wait_group %0;" :: "n"(N) : "memory")

static __device__ __forceinline__ uint32_t h2pack(float lo, float hi) {
    uint32_t p;
    asm("cvt.rn.f16x2.f32 %0, %1, %2;" : "=r"(p) : "f"(hi), "f"(lo));
    return p;
}

// ---------------------------------------------------------------------------
// Kernel 0a: z -> fp16(-2z); zero loss
// ---------------------------------------------------------------------------
__global__ void zconv_kernel(const float* __restrict__ z) {
    if (blockIdx.x == 0 && threadIdx.x == 0) g_loss = 0.0;
    int i = blockIdx.x * blockDim.x + threadIdx.x;     // < 1048576
    const float4* z4 = reinterpret_cast<const float4*>(z);
    float4 a = z4[i * 2], b = z4[i * 2 + 1];
    uint4 o;
    o.x = h2pack(-2.f * a.x, -2.f * a.y);
    o.y = h2pack(-2.f * a.z, -2.f * a.w);
    o.z = h2pack(-2.f * b.x, -2.f * b.y);
    o.w = h2pack(-2.f * b.z, -2.f * b.w);
    g_zh4[i] = o;
}

// ---------------------------------------------------------------------------
// Kernel 0b: emb -> fp16 + ||e||^2
// ---------------------------------------------------------------------------
__global__ void econv_kernel(const float* __restrict__ emb) {
    int w = (blockIdx.x * blockDim.x + threadIdx.x) >> 5;   // code
    int l = threadIdx.x & 31;
    float4 v = reinterpret_cast<const float4*>(emb)[w * 32 + l];
    float s = v.x * v.x + v.y * v.y + v.z * v.z + v.w * v.w;
    #pragma unroll
    for (int o = 16; o > 0; o >>= 1) s += __shfl_xor_sync(0xffffffffu, s, o);
    if (l == 0) g_enorm[w] = s;
    uint2 p;
    p.x = h2pack(v.x, v.y);
    p.y = h2pack(v.z, v.w);
    reinterpret_cast<uint2*>(g_eh4)[w * 32 + l] = p;
}

// ---------------------------------------------------------------------------
// Kernel 1: fp16 mma.sync GEMM (f16 acc), 512 threads, top-3/stream
// ---------------------------------------------------------------------------
#define TOP3(sl, s, c) do {                                                     \
    if ((s) < bv2[sl]) {                                                        \
        if ((s) < bv0[sl]) { bv2[sl]=bv1[sl]; bi2[sl]=bi1[sl];                  \
                             bv1[sl]=bv0[sl]; bi1[sl]=bi0[sl];                  \
                             bv0[sl]=(s);     bi0[sl]=(c); }                    \
        else if ((s) < bv1[sl]) { bv2[sl]=bv1[sl]; bi2[sl]=bi1[sl];             \
                                  bv1[sl]=(s);     bi1[sl]=(c); }               \
        else { bv2[sl]=(s); bi2[sl]=(c); }                                      \
    } } while (0)

__global__ void __launch_bounds__(512, 1) vq_mma_kernel() {
    extern __shared__ char smraw[];
    uint32_t sb0 = smem_u32(smraw);
    uint32_t base = (sb0 + 1023u) & ~1023u;

    const int tid = threadIdx.x;
    const int wid = tid >> 5;
    const int l   = tid & 31;
    const int wm  = wid >> 3;      // 0..1 : 64-row group
    const int wn  = wid & 7;       // 0..7 : 16-code column
    const int row0 = blockIdx.x * TM;

    // ---- A tile + B tile 0, swizzle chunk' = c ^ (r&7) ----
    {
        const char* srcA = reinterpret_cast<const char*>(g_zh4) + (size_t)row0 * 256;
        const char* srcB = reinterpret_cast<const char*>(g_eh4);
        #pragma unroll
        for (int i = 0; i < 4; ++i) {
            int f = i * 512 + tid;
            int r = f >> 4, c = f & 15;
            uint32_t so = r * 256 + ((c ^ (r & 7)) << 4);
            CP_ASYNC16(base + SA + so, srcA + r * 256 + c * 16);
            CP_ASYNC16(base + SB + so, srcB + r * 256 + c * 16);
        }
    }
    CP_COMMIT();

    // ---- fragment addresses ----
    uint32_t aab[4], bab;
    {
        int arow_l = ((l >> 3) & 1) * 8 + (l & 7);
        #pragma unroll
        for (int mf = 0; mf < 4; ++mf)
            aab[mf] = base + SA + (wm * 64 + mf * 16 + arow_l) * 256;
        int brow_l = ((l >> 4) & 1) * 8 + (l & 7);
        bab = (wn * 16 + brow_l) * 256;
    }
    const int asel = (l >> 4) & 1;
    const int bsel = (l >> 3) & 1;
    const int sw   = l & 7;

    float bv0[8], bv1[8], bv2[8];
    int   bi0[8], bi1[8], bi2[8];
    #pragma unroll
    for (int s = 0; s < 8; ++s) {
        bv0[s] = bv1[s] = bv2[s] = 3.4e38f;
        bi0[s] = bi1[s] = bi2[s] = 0;
    }

    for (int kt = 0; kt < NT; ++kt) {
        __syncthreads();   // everyone done reading the buffer being overwritten
        if (kt + 1 < NT) {
            const char* srcb = reinterpret_cast<const char*>(g_eh4) +
                               (size_t)(kt + 1) * TN * 256;
            uint32_t dstb = base + SB + ((kt + 1) & 1) * 32768;
            #pragma unroll
            for (int i = 0; i < 4; ++i) {
                int f = i * 512 + tid;
                int r = f >> 4, c = f & 15;
                CP_ASYNC16(dstb + r * 256 + ((c ^ (r & 7)) << 4), srcb + r * 256 + c * 16);
            }
            CP_COMMIT();
            CP_WAIT(1);
        } else {
            CP_WAIT(0);
        }
        __syncthreads();   // B(kt) (and A at kt=0) visible

        const uint32_t bufb = base + SB + (kt & 1) * 32768;

        uint32_t acc[4][2][2];   // [mf][nf][2 regs of f16x2], init 0
        #pragma unroll
        for (int mf = 0; mf < 4; ++mf)
            #pragma unroll
            for (int nf = 0; nf < 2; ++nf) { acc[mf][nf][0] = 0u; acc[mf][nf][1] = 0u; }

        #pragma unroll
        for (int ks = 0; ks < 8; ++ks) {
            const int c2 = 2 * ks;
            uint32_t Af[4][4], Bf[4];
            const uint32_t aoff = (uint32_t)((c2 + asel) ^ sw) << 4;
            const uint32_t boff = (uint32_t)((c2 + bsel) ^ sw) << 4;
            #pragma unroll
            for (int mf = 0; mf < 4; ++mf) ldsm4(Af[mf], aab[mf] + aoff);
            ldsm4(Bf, bufb + bab + boff);
            #pragma unroll
            for (int mf = 0; mf < 4; ++mf) {
                mma16816h(acc[mf][0], Af[mf], Bf[0], Bf[1]);
                mma16816h(acc[mf][1], Af[mf], Bf[2], Bf[3]);
            }
        }

        // ---- epilogue: unpack f16 scores + bias + top-3 ----
        #pragma unroll
        for (int nf = 0; nf < 2; ++nf) {
            const int cidx = kt * 128 + wn * 16 + nf * 8 + 2 * (l & 3);
            const float2 bp = __ldg(reinterpret_cast<const float2*>(g_enorm + cidx));
            #pragma unroll
            for (int mf = 0; mf < 4; ++mf) {
                float2 lo = __half22float2(*reinterpret_cast<__half2*>(&acc[mf][nf][0]));
                float2 hi = __half22float2(*reinterpret_cast<__half2*>(&acc[mf][nf][1]));
                float s0 = lo.x + bp.x;
                float s1 = lo.y + bp.y;
                float s2 = hi.x + bp.x;
                float s3 = hi.y + bp.y;
                TOP3(mf * 2,     s0, cidx);
                TOP3(mf * 2,     s1, cidx + 1);
                TOP3(mf * 2 + 1, s2, cidx);
                TOP3(mf * 2 + 1, s3, cidx + 1);
            }
        }
    }

    // ---- candidate writeout: 32 stream-positions x 3 per row ----
    #pragma unroll
    for (int s = 0; s < 8; ++s) {
        int row = row0 + wm * 64 + (s >> 1) * 16 + (s & 1) * 8 + (l >> 2);
        int p = wn * 4 + (l & 3);
        int*   d  = g_cand  + (size_t)row * NCAND + p * 3;
        float* dv = g_candv + (size_t)row * NCAND + p * 3;
        d[0]  = bi0[s]; d[1]  = bi1[s]; d[2]  = bi2[s];
        dv[0] = bv0[s]; dv[1] = bv1[s]; dv[2] = bv2[s];
    }
}

// ---------------------------------------------------------------------------
// Kernel 2: filtered exact rescore (warp per row; ~1 exact dot per row)
// ---------------------------------------------------------------------------
__global__ void __launch_bounds__(256) rescore_kernel(const float* __restrict__ z,
                                                      const float* __restrict__ emb) {
    __shared__ double wloss[8];
    const int w = threadIdx.x >> 5;
    const int l = threadIdx.x & 31;
    const int r = blockIdx.x * 8 + w;

    float4 zv = reinterpret_cast<const float4*>(z)[(size_t)r * 32 + l];
    float zsq = zv.x * zv.x + zv.y * zv.y + zv.z * zv.z + zv.w * zv.w;
    #pragma unroll
    for (int o = 16; o > 0; o >>= 1) zsq += __shfl_xor_sync(0xffffffffu, zsq, o);

    // lane l owns candidate slots l*3 .. l*3+2
    int   c0 = g_cand [(size_t)r * NCAND + l * 3 + 0];
    int   c1 = g_cand [(size_t)r * NCAND + l * 3 + 1];
    int   c2 = g_cand [(size_t)r * NCAND + l * 3 + 2];
    float v0 = g_candv[(size_t)r * NCAND + l * 3 + 0];
    float v1 = g_candv[(size_t)r * NCAND + l * 3 + 1];
    float v2 = g_candv[(size_t)r * NCAND + l * 3 + 2];

    float m = fminf(v0, fminf(v1, v2));
    #pragma unroll
    for (int o = 16; o > 0; o >>= 1) m = fminf(m, __shfl_xor_sync(0xffffffffu, m, o));
    const float thr = m + EPSF;

    float bestv = 3.4e38f;
    int   besti = 0x7fffffff;
    #pragma unroll
    for (int i = 0; i < 3; ++i) {
        int   ci = (i == 0) ? c0 : (i == 1) ? c1 : c2;
        float vi = (i == 0) ? v0 : (i == 1) ? v1 : v2;
        unsigned msk = __ballot_sync(0xffffffffu, vi <= thr);
        while (msk) {
            int b = __ffs(msk) - 1;
            msk &= msk - 1;
            int c = __shfl_sync(0xffffffffu, ci, b);
            float4 ev = reinterpret_cast<const float4*>(emb)[(size_t)c * 32 + l];
            float d = zv.x * ev.x + zv.y * ev.y + zv.z * ev.z + zv.w * ev.w;
            #pragma unroll
            for (int o = 16; o > 0; o >>= 1) d += __shfl_xor_sync(0xffffffffu, d, o);
            float sc = fmaf(-2.f, d, __ldg(&g_enorm[c]));
            if (sc < bestv || (sc == bestv && c < besti)) { bestv = sc; besti = c; }
        }
    }

    if (l == 0) {
        g_idx[r] = besti;
        wloss[w] = (double)(zsq + bestv);
    }
    __syncthreads();
    if (threadIdx.x == 0) {
        double s = 0.0;
        #pragma unroll
        for (int i = 0; i < 8; ++i) s += wloss[i];
        atomicAdd(&g_loss, s);
    }
}

// ---------------------------------------------------------------------------
// Kernel 3: gather + transpose to [B, D, H, W]
// ---------------------------------------------------------------------------
__global__ void gather_kernel(const float* __restrict__ emb, float* __restrict__ out) {
    int hw = blockIdx.x * blockDim.x + threadIdx.x;  // 0..4095
    int d4 = blockIdx.y;                             // 0..31
    int b  = blockIdx.z;                             // 0..15
    int id = g_idx[b * HW + hw];
    float4 e = __ldg(reinterpret_cast<const float4*>(emb) + (size_t)id * 32 + d4);
    size_t ob = ((size_t)b * DDIM + d4 * 4) * HW + hw;
    out[ob]          = e.x;
    out[ob + HW]     = e.y;
    out[ob + 2 * HW] = e.z;
    out[ob + 3 * HW] = e.w;
}

// ---------------------------------------------------------------------------
// Kernel 4: scalar loss = 1.25 * mean(||z_q - z||^2)
// ---------------------------------------------------------------------------
__global__ void loss_kernel(float* __restrict__ out) {
    out[NELEM] = (float)(1.25 * g_loss / (double)NELEM);
}

// ---------------------------------------------------------------------------
extern "C" void kernel_launch(void* const* d_in, const int* in_sizes, int n_in,
                              void* d_out, int out_size) {
    const float* z   = (const float*)d_in[0];   // [16,64,64,128] fp32
    const float* emb = (const float*)d_in[1];   // [4096,128] fp32
    float* out = (float*)d_out;

    cudaFuncSetAttribute(vq_mma_kernel, cudaFuncAttributeMaxDynamicSharedMemorySize,
                         SMEM_TOT);

    zconv_kernel<<<4096, 256>>>(z);
    econv_kernel<<<512, 256>>>(emb);
    vq_mma_kernel<<<NROWS / TM, 512, SMEM_TOT>>>();
    rescore_kernel<<<NROWS / 8, 256>>>(z, emb);
    gather_kernel<<<dim3(HW / 256, DDIM / 4, BATCH), 256>>>(emb, out);
    if (out_size > NELEM) loss_kernel<<<1, 1>>>(out);
}